// round 1
// baseline (speedup 1.0000x reference)
#include <cuda_runtime.h>

// HDCProcessor: causal decayed-average of trigram-bound hypervectors.
//   hdc[b,t,d] = 0.3*cb[i_t,d] + 0.7*cb[i_t,d]*cb[i_{t-1},(d-1)%D]*cb[i_{t-2},(d-2)%D]
//   out[b,t,d] = (1-g)/(1-g^{t+1}) * sum_{s<=t} g^{t-s} hdc[b,s,d],  g = 0.95
// Implemented as an exponential-decay scan over t (NOT the T x T matmul).
// T is split into 4 chunks; chunks 1..3 warm the accumulator up for WUP steps
// (dropped tail <= 0.95^289 ~ 3.7e-7 absolute, below the reference's own fp32
// rounding noise). Chunk lengths 728/440/440/440 make every chain exactly
// NSTEPS = 728 steps -> balanced grid.

#define DDIM    4096
#define NB      8
#define NT      2048
#define DECAYF  0.95f
#define NCHUNK  4
#define L0      728
#define LI      440
#define WUP     288            // warmup steps for chunks 1..3 (WUP + LI == L0)
#define NSTEPS  728            // uniform chain length for every block
#define NTHREADS 128
#define DPT     4              // dims per thread (float4)
#define DPB     (NTHREADS*DPT) // 512 dims per block
#define NDG     (DDIM/DPB)     // 8 d-groups
#define PF      4              // prefetch depth (circular reg buffer)
#define SIDX_N  736            // NSTEPS + 2 history + PF pad, rounded

__global__ void __launch_bounds__(NTHREADS)
hdc_scan_kernel(const float* __restrict__ cb,
                const int*   __restrict__ idx,
                float*       __restrict__ out)
{
    const int dg    = blockIdx.x;   // which 512-wide slice of D
    const int chunk = blockIdx.y;   // which T chunk
    const int b     = blockIdx.z;

    const int t0    = (chunk == 0) ? 0 : (L0 + (chunk - 1) * LI);
    const int len   = (chunk == 0) ? L0 : LI;
    const int nwarm = NSTEPS - len;       // 0 or WUP
    const int ts    = t0 - nwarm;         // first scanned timestep (>= 0)

    const int tid  = threadIdx.x;
    const int lane = tid & 31;
    const int wid  = tid >> 5;
    const int d    = dg * DPB + tid * DPT;        // this thread's base dim
    const int db   = dg * DPB + wid * 128;        // warp base dim
    const int dm2  = (db + DDIM - 2) & (DDIM - 1);// warp-boundary cols d-2,d-1
    const bool l0  = (lane == 0);

    __shared__ int   s_idx[SIDX_N];
    __shared__ float s_inv[L0];

    // Stage idx[b, ts-2 .. t0+len-1] in smem; pad tail/negatives with row 0
    // (padded rows are only ever loaded, never used in math).
    const int base_t = ts - 2;
    const int n_idx  = NSTEPS + 2;
    const int* idxb  = idx + b * NT;
    for (int k = tid; k < SIDX_N; k += NTHREADS) {
        int t = base_t + k;
        s_idx[k] = (k < n_idx && t >= 0) ? idxb[t] : 0;
    }
    // Row-normalization table: inv[t] = (1-g)/(1-g^{t+1})
    for (int k = tid; k < len; k += NTHREADS) {
        double p = pow(0.95, (double)(t0 + k + 1));
        s_inv[k] = (float)(0.05 / (1.0 - p));
    }
    __syncthreads();

    // Row-value history: h1 = cb[i_{t-1}][d..d+3], h2 = cb[i_{t-2}][d..d+3].
    // eh1/eh2 (lane 0 only): cols [db-2, db-1] of those rows, for the
    // cross-warp shift boundary. Zero-init for chunk 0 reproduces the
    // reference's zeroed chars_m1/chars_m2 rows at t = 0,1 exactly.
    float4 h1, h2;
    float2 eh1, eh2;
    if (chunk == 0) {
        h1 = make_float4(0.f, 0.f, 0.f, 0.f); h2 = h1;
        eh1 = make_float2(0.f, 0.f); eh2 = eh1;
    } else {
        int i1 = s_idx[1];  // idx at ts-1
        int i2 = s_idx[0];  // idx at ts-2
        h1 = *reinterpret_cast<const float4*>(cb + (size_t)i1 * DDIM + d);
        h2 = *reinterpret_cast<const float4*>(cb + (size_t)i2 * DDIM + d);
        eh1 = make_float2(0.f, 0.f); eh2 = eh1;
        if (l0) {
            eh1 = *reinterpret_cast<const float2*>(cb + (size_t)i1 * DDIM + dm2);
            eh2 = *reinterpret_cast<const float2*>(cb + (size_t)i2 * DDIM + dm2);
        }
    }

    // Prefetch pipeline (depth PF): current-row values + lane-0 boundary pair.
    float4 cbuf[PF];
    float2 ebuf[PF];
#pragma unroll
    for (int j = 0; j < PF; j++) {
        int row = s_idx[2 + j];
        cbuf[j] = *reinterpret_cast<const float4*>(cb + (size_t)row * DDIM + d);
        ebuf[j] = make_float2(0.f, 0.f);
        if (l0)
            ebuf[j] = *reinterpret_cast<const float2*>(cb + (size_t)row * DDIM + dm2);
    }

    float4 acc = make_float4(0.f, 0.f, 0.f, 0.f);
    float* outb = out + (size_t)b * NT * DDIM + d;

#pragma unroll 4
    for (int step = 0; step < NSTEPS; step++) {
        const int bi = step & (PF - 1);
        float4 cur = cbuf[bi];
        float2 e   = ebuf[bi];

        // Prefetch step+PF (tail reads padded row 0, harmless).
        {
            int row = s_idx[2 + step + PF];
            cbuf[bi] = *reinterpret_cast<const float4*>(cb + (size_t)row * DDIM + d);
            if (l0)
                ebuf[bi] = *reinterpret_cast<const float2*>(cb + (size_t)row * DDIM + dm2);
        }

        // Shifted history: m1[j] = cb[i_{t-1}][d+j-1], m2[j] = cb[i_{t-2}][d+j-2]
        float a1 = __shfl_up_sync(0xffffffffu, h1.w, 1);
        float a2 = __shfl_up_sync(0xffffffffu, h2.z, 1);
        float a3 = __shfl_up_sync(0xffffffffu, h2.w, 1);
        if (l0) { a1 = eh1.y; a2 = eh2.x; a3 = eh2.y; }

        const float m1x = a1,   m1y = h1.x, m1z = h1.y, m1w = h1.z;
        const float m2x = a2,   m2y = a3,   m2z = h2.x, m2w = h2.y;

        // hdc = cur * (0.3 + 0.7 * m1 * m2);  acc = 0.95*acc + hdc
        acc.x = DECAYF * acc.x + cur.x * (0.3f + 0.7f * (m1x * m2x));
        acc.y = DECAYF * acc.y + cur.y * (0.3f + 0.7f * (m1y * m2y));
        acc.z = DECAYF * acc.z + cur.z * (0.3f + 0.7f * (m1z * m2z));
        acc.w = DECAYF * acc.w + cur.w * (0.3f + 0.7f * (m1w * m2w));

        if (step >= nwarm) {
            const float inv = s_inv[step - nwarm];
            const int t = ts + step;
            float4 o = make_float4(acc.x * inv, acc.y * inv,
                                   acc.z * inv, acc.w * inv);
            *reinterpret_cast<float4*>(outb + (size_t)t * DDIM) = o;
        }

        h2 = h1; h1 = cur;
        eh2 = eh1; eh1 = e;
    }
}

extern "C" void kernel_launch(void* const* d_in, const int* in_sizes, int n_in,
                              void* d_out, int out_size)
{
    const float* cb  = (const float*)d_in[0];   // (256, 4096) f32 bipolar
    const int*   idx = (const int*)d_in[1];     // (8, 2048) i32
    float*       out = (float*)d_out;           // (8, 2048, 4096) f32

    dim3 grid(NDG, NCHUNK, NB);                 // 8 x 4 x 8 = 256 blocks
    hdc_scan_kernel<<<grid, NTHREADS>>>(cb, idx, out);
}

// round 2
// speedup vs baseline: 1.3031x; 1.3031x over previous
#include <cuda_runtime.h>
#include <cstdint>

// HDCProcessor as a bit-domain exponential-decay scan.
//   codebook is bipolar (+-1): only the sign bit carries information.
//   hdc[t,d] = 0.3*s(t,d) + 0.7*s(t,d)*s(t-1,d-1)*s(t-2,d-2)   (rolls mod D)
//   out[t]   = (1-g)/(1-g^{t+1}) * sum_{s<=t} g^{t-s} hdc[s],  g=0.95
// Pre-pass packs sign bits (256 rows x 4096 bits = 128KB). Scan blocks stage
// their 512-bit slice (+32-bit halo for the rolls, incl. the D-wrap) in smem;
// the main loop has ZERO global loads. T split into 16 chunks of 128 with a
// 176-step warmup (truncation ~1.2e-4 rel, gate is 1e-3) -> 1024 blocks,
// ~7 blocks / 28 warps per SM, single wave.

#define DDIM     4096
#define NB       8
#define NT       2048
#define NCHUNK   16
#define CLEN     128
#define WUP      176
#define NTHREADS 128
#define NDG      8            // 4096 / (128 threads * 4 dims)
#define ROWW     17           // smem words per row: 1 halo + 16 slice
#define SIDX     312          // >= max_nsteps(304) + 2

__device__ uint32_t g_packed[256 * 128];   // bit k of word w of row r = sign<0

__global__ void pack_kernel(const float* __restrict__ cb) {
    const int row  = blockIdx.x;
    const int lane = threadIdx.x & 31;
    const int wd   = threadIdx.x >> 5;
    for (int w = wd; w < 128; w += 4) {
        float v = cb[row * DDIM + w * 32 + lane];
        unsigned m = __ballot_sync(0xffffffffu, v < 0.0f);
        if (lane == 0) g_packed[row * 128 + w] = m;
    }
}

__global__ void __launch_bounds__(NTHREADS)
scan_kernel(const int* __restrict__ idx, float* __restrict__ out)
{
    const int dg    = blockIdx.x;
    const int chunk = blockIdx.y;
    const int b     = blockIdx.z;

    const int t0     = chunk * CLEN;
    const int ts     = (t0 - WUP > 0) ? (t0 - WUP) : 0;  // first scanned t
    const int nwarm  = t0 - ts;
    const int nsteps = nwarm + CLEN;

    const int tid = threadIdx.x;

    __shared__ uint32_t s_bits[256 * ROWW + 1];  // +1: funnel hi-word pad
    __shared__ int      s_idx[SIDX];
    __shared__ float    s_inv[CLEN];

    // ---- stage packed codebook slice: word 0 = halo (global bits d0-32..d0-1,
    // wrapped mod 4096), words 1..16 = the 512-bit slice ----
    const int slice0 = dg * 16;                     // first global word of slice
    const int halow  = (slice0 - 1) & 127;          // halo word (handles D-wrap)
    for (int k = tid; k < 256 * ROWW; k += NTHREADS) {
        int row = k / ROWW;
        int w   = k - row * ROWW;
        int gw  = (w == 0) ? halow : (slice0 + w - 1);
        s_bits[k] = g_packed[row * 128 + gw];
    }
    if (tid == 0) s_bits[256 * ROWW] = 0;

    // ---- stage idx[b, ts-2 .. ts+nsteps-1]; t<0 padded with row 0 (masked) ----
    const int* idxb = idx + b * NT;
    for (int k = tid; k < SIDX; k += NTHREADS) {
        int t = ts - 2 + k;
        s_idx[k] = (k < nsteps + 2 && t >= 0) ? idxb[t] : 0;
    }
    // ---- row-normalization: inv[k] = (1-g)/(1-g^{t0+k+1}) ----
    if (tid < CLEN) {
        double p = pow(0.95, (double)(t0 + tid + 1));
        s_inv[tid] = (float)(0.05 / (1.0 - p));
    }
    __syncthreads();

    // Per-thread 6-bit field position within a row bitstring:
    // bit (32 + m) = global dim (dg*512 + m). Field covers global dims d-2..d+3.
    const int p   = 30 + 4 * tid;          // bit index of (d-2)
    const int q   = p >> 5;
    const int rsh = p & 31;

    float acc0 = 0.f, acc1 = 0.f, acc2 = 0.f, acc3 = 0.f;
    uint32_t f1 = 0, f2 = 0;               // fields of rows t-1, t-2
    if (ts >= 2) {                          // real history (ts>=2 => t-1,t-2 valid)
        int i1 = s_idx[1], i2 = s_idx[0];
        f1 = __funnelshift_r(s_bits[i1 * ROWW + q], s_bits[i1 * ROWW + q + 1], rsh);
        f2 = __funnelshift_r(s_bits[i2 * ROWW + q], s_bits[i2 * ROWW + q + 1], rsh);
    }

    float* op = out + ((size_t)b * NT + t0) * DDIM + dg * 512 + 4 * tid;

#pragma unroll 4
    for (int step = 0; step < nsteps; step++) {
        const int i_t = s_idx[step + 2];
        const int rb  = i_t * ROWW;
        const uint32_t f = __funnelshift_r(s_bits[rb + q], s_bits[rb + q + 1], rsh);

        // y bit j = cur(d+j) ^ m1(d+j-1) ^ m2(d+j-2);  cur bit j at f>>(2+j)
        const uint32_t y = (f >> 2) ^ (f1 >> 1) ^ f2;

        // t<2: reference zeroes the shifted-history rows -> trigram term = 0
        const float w07 = ((ts + step) < 2) ? 0.0f : 0.7f;

        // c_j = 0.3*s_cur + w07*s_trig ; sign built by OR into 1.0f
#define MKC(j, accv)                                                          \
        {                                                                     \
            uint32_t ub = ((f << (29 - j)) & 0x80000000u) | 0x3F800000u;      \
            uint32_t vb = ((y << (31 - j)) & 0x80000000u) | 0x3F800000u;      \
            float c = fmaf(w07, __uint_as_float(vb),                          \
                           0.3f * __uint_as_float(ub));                       \
            accv = fmaf(0.95f, accv, c);                                      \
        }
        MKC(0, acc0) MKC(1, acc1) MKC(2, acc2) MKC(3, acc3)
#undef MKC

        if (step >= nwarm) {
            const float inv = s_inv[step - nwarm];
            float4 o = make_float4(acc0 * inv, acc1 * inv, acc2 * inv, acc3 * inv);
            *reinterpret_cast<float4*>(op) = o;
            op += DDIM;
        }

        f2 = f1; f1 = f;
    }
}

extern "C" void kernel_launch(void* const* d_in, const int* in_sizes, int n_in,
                              void* d_out, int out_size)
{
    const float* cb  = (const float*)d_in[0];   // (256, 4096) f32 bipolar
    const int*   idx = (const int*)d_in[1];     // (8, 2048) i32
    float*       out = (float*)d_out;           // (8, 2048, 4096) f32

    pack_kernel<<<256, 128>>>(cb);
    dim3 grid(NDG, NCHUNK, NB);                 // 8 x 16 x 8 = 1024 blocks
    scan_kernel<<<grid, NTHREADS>>>(idx, out);
}